// round 9
// baseline (speedup 1.0000x reference)
#include <cuda_runtime.h>
#include <cstdint>

#define TH 1.0f
#define EPS_BN 1e-5f

// scratch (no allocations allowed -> device globals)
__device__ float g_dm[256 * 256];
__device__ int   g_rowok[256];
__device__ int   g_done = 0;   // reset to 0 by the last block each run (replay-safe)

__device__ __forceinline__ uint32_t smem_u32(const void* p) {
    uint32_t a;
    asm("{ .reg .u64 t; cvta.to.shared.u64 t, %1; cvt.u32.u64 %0, t; }"
        : "=r"(a) : "l"(p));
    return a;
}

// ---------------------------------------------------------------------------
// Single fused kernel, 2304 blocks x 256 threads:
//  blocks 0..255 : dm row n = b. Thread m computes dm[n][m] into smem (1KB)
//    and g_dm. Then 128 TMA bulk S2G copies (1KB each) broadcast the row into
//    dist_mat_full[t][n][:] for all t — stores bypass L1 entirely.
//    Done-counter; LAST block computes group_indices in-kernel
//    (fast path all-zeros; exact lax.scan replica fallback).
//  blocks 256..2303 : float4 slab copy v_rel -> v_grouped
//    (stop_gradient(v - v_soft) + v_soft == v exactly).
// ---------------------------------------------------------------------------
__global__ void fused_kernel(const float* __restrict__ v,
                             const float* __restrict__ w1,
                             const float* __restrict__ b1,
                             const float* __restrict__ bn_gamma,
                             const float* __restrict__ bn_beta,
                             const float* __restrict__ bn_mean,
                             const float* __restrict__ bn_var,
                             const float* __restrict__ w2,
                             const float* __restrict__ b2,
                             float* __restrict__ out) {
    int b = blockIdx.x;
    int tid = threadIdx.x;

    if (b >= 256) {
        // ---- copy part: v_grouped = v_rel (2M float4 over 2048 blocks) ----
        const float4* __restrict__ v4 = (const float4*)v;
        float4* __restrict__ ov = (float4*)out;
        int i0 = (b - 256) * 1024 + tid;
        float4 r0 = v4[i0];
        float4 r1 = v4[i0 + 256];
        float4 r2 = v4[i0 + 512];
        float4 r3 = v4[i0 + 768];
        __stcs(&ov[i0],       r0);
        __stcs(&ov[i0 + 256], r1);
        __stcs(&ov[i0 + 512], r2);
        __stcs(&ov[i0 + 768], r3);
        return;
    }

    // ---- dm + TMA dist broadcast part ----
    __shared__ __align__(1024) float srow[256];
    __shared__ float sa[32], sw0[32], sw1[32], sb[32];
    __shared__ float sK;
    __shared__ int s_islast;
    if (tid < 32) {
        float scale = bn_gamma[tid] * rsqrtf(bn_var[tid] + EPS_BN);
        float w2o = w2[tid];
        sa[tid]  = w2o * scale;
        sw0[tid] = w1[tid * 2 + 0];
        sw1[tid] = w1[tid * 2 + 1];
        sb[tid]  = b1[tid];
        float kpart = w2o * (bn_beta[tid] - bn_mean[tid] * scale);
        #pragma unroll
        for (int off = 16; off > 0; off >>= 1)
            kpart += __shfl_down_sync(0xffffffffu, kpart, off);
        if (tid == 0) sK = kpart + b2[0];
    }
    __syncthreads();

    int n = b;
    int m = tid;
    // x[c][i] = v_rel[0, c, 127, i], layout (1,256,128,256)
    const int base = 127 * 256;
    float d0 = v[base + n] - v[base + m];
    float d1 = v[32768 + base + n] - v[32768 + base + m];

    float sp = sK, sn = sK;
    #pragma unroll
    for (int o = 0; o < 32; o++) {
        float lin = sw0[o] * d0 + sw1[o] * d1;
        sp += sa[o] * fmaxf(lin + sb[o], 0.0f);
        sn += sa[o] * fmaxf(sb[o] - lin, 0.0f);
    }
    float val = 0.5f * (expf(sp) + expf(sn));
    srow[m] = val;
    g_dm[n * 256 + m] = val;

    int anyok = __syncthreads_or((m < n) && (val <= TH));   // also orders srow
    if (tid == 0) g_rowok[n] = anyok;

    // make generic smem stores visible to the async proxy, then broadcast:
    // 128 bulk S2G copies of the 1KB row -> dist_mat_full[t*65536 + n*256]
    asm volatile("fence.proxy.async.shared::cta;" ::: "memory");

    int lane = tid & 31;
    int w = tid >> 5;
    if (lane == 0) {
        uint32_t sbuf = smem_u32(srow);
        float* dbase = out + 8388864 + n * 256 + (long)w * 16 * 65536;
        #pragma unroll
        for (int k = 0; k < 16; k++) {
            float* dst = dbase + (long)k * 65536;
            asm volatile(
                "cp.async.bulk.global.shared::cta.bulk_group [%0], [%1], %2;"
                :: "l"(dst), "r"(sbuf), "r"(1024u) : "memory");
        }
        asm volatile("cp.async.bulk.commit_group;" ::: "memory");
        asm volatile("cp.async.bulk.wait_group 0;" ::: "memory");
    }

    // ---- done-counter handshake: last block computes groups ----
    if (tid == 0) {
        __threadfence();                       // commit g_dm row + rowok
        int old = atomicAdd(&g_done, 1);
        s_islast = (old == 255);
    }
    __syncthreads();
    if (!s_islast) return;
    __threadfence();                           // see all rows' writes

    float* __restrict__ out_gi = out + 8388608;
    int rowok = g_rowok[tid];
    bool fast = __syncthreads_and(tid == 0 || rowok);
    if (fast) {
        // every row r>=1 merges into the component labeled 0 -> all ranks 0
        out_gi[tid] = 0.0f;
    } else {
        // ---- exact fallback: row-parallel replica of reference lax.scan ----
        __shared__ int comp[256];
        __shared__ int firstidx[256];
        __shared__ int marked[256];
        __shared__ int cstar;
        __shared__ int newcomp;
        comp[tid] = tid;
        __syncthreads();

        for (int r = 1; r < 256; r++) {
            firstidx[tid] = 0x7fffffff;
            marked[tid] = 0;
            if (tid == 0) cstar = -1;
            __syncthreads();

            int myc = comp[tid];
            int rcomp = comp[r];
            bool okc = (tid < r) && (g_dm[r * 256 + tid] <= TH);
            if (okc) {
                atomicMin(&firstidx[myc], tid);
                marked[myc] = 1;
            }
            if (tid == r) marked[myc] = 1;
            __syncthreads();

            if (okc && myc != rcomp && firstidx[myc] == tid)
                atomicMax(&cstar, tid);
            __syncthreads();

            int cs = cstar;
            if (cs >= 0 && tid == cs) newcomp = myc;
            __syncthreads();
            if (cs >= 0 && marked[myc]) comp[tid] = newcomp;
            __syncthreads();
        }

        __shared__ int pres[256];
        pres[tid] = 0;
        __syncthreads();
        pres[comp[tid]] = 1;
        __syncthreads();
        for (int off = 1; off < 256; off <<= 1) {
            int t = (tid >= off) ? pres[tid - off] : 0;
            __syncthreads();
            pres[tid] += t;
            __syncthreads();
        }
        out_gi[tid] = (float)(pres[comp[tid]] - 1);
    }
    __syncthreads();
    if (tid == 0) g_done = 0;                  // reset for next graph replay
}

extern "C" void kernel_launch(void* const* d_in, const int* in_sizes, int n_in,
                              void* d_out, int out_size) {
    const float* v_rel    = (const float*)d_in[0];
    const float* w1       = (const float*)d_in[1];
    const float* b1       = (const float*)d_in[2];
    const float* bn_gamma = (const float*)d_in[3];
    const float* bn_beta  = (const float*)d_in[4];
    const float* bn_mean  = (const float*)d_in[5];
    const float* bn_var   = (const float*)d_in[6];
    const float* w2       = (const float*)d_in[7];
    const float* b2       = (const float*)d_in[8];
    float* out = (float*)d_out;

    fused_kernel<<<2304, 256>>>(v_rel, w1, b1, bn_gamma, bn_beta, bn_mean,
                                bn_var, w2, b2, out);
}

// round 12
// speedup vs baseline: 1.0153x; 1.0153x over previous
#include <cuda_runtime.h>
#include <cstdint>

#define TH 1.0f
#define EPS_BN 1e-5f

// scratch (no allocations allowed -> device globals)
__device__ float g_dm[256 * 256];
__device__ int   g_rowok[256];
__device__ int   g_done = 0;   // reset to 0 by the last block each run (replay-safe)

struct U4 { unsigned long long x, y, z, w; };

// L2-resident 256-bit store (sm_103a requires v4.b64/v8.b32 for evict hints).
__device__ __forceinline__ void st_res(void* p, U4 v) {
    asm volatile("st.global.L2::evict_last.v4.b64 [%0], {%1,%2,%3,%4};"
                 :: "l"(p), "l"(v.x), "l"(v.y), "l"(v.z), "l"(v.w) : "memory");
}
// Streaming 256-bit input load: don't let v evict the resident output.
__device__ __forceinline__ U4 ld_stream(const void* p) {
    U4 v;
    asm volatile("ld.global.nc.L2::evict_first.v4.b64 {%0,%1,%2,%3}, [%4];"
                 : "=l"(v.x), "=l"(v.y), "=l"(v.z), "=l"(v.w) : "l"(p));
    return v;
}

// ---------------------------------------------------------------------------
// Single fused kernel, 2560 blocks x 256 threads:
//  blocks 0..511 : dm row n = b>>1, slice s = b&1. Compute the MLP row
//    (thread m -> dm[n][m]) into shared, write 64 t-copies into
//    dist_mat_full (t in [s*64, s*64+64)) as 32B resident stores. Slice 0
//    stores g_dm row + rowok[n] and joins a done-counter; the LAST slice-0
//    block computes group_indices in-kernel (fast path all-zeros; exact
//    lax.scan replica fallback).
//  blocks 512..2559 : 32B-chunk copy v_rel -> v_grouped
//    (stop_gradient(v - v_soft) + v_soft == v exactly).
// Output stores L2::evict_last (stay resident; rewritten every replay);
// v loads L2::evict_first (stream through).
// ---------------------------------------------------------------------------
__global__ void fused_kernel(const float* __restrict__ v,
                             const float* __restrict__ w1,
                             const float* __restrict__ b1,
                             const float* __restrict__ bn_gamma,
                             const float* __restrict__ bn_beta,
                             const float* __restrict__ bn_mean,
                             const float* __restrict__ bn_var,
                             const float* __restrict__ w2,
                             const float* __restrict__ b2,
                             float* __restrict__ out) {
    int b = blockIdx.x;
    int tid = threadIdx.x;

    if (b >= 512) {
        // ---- copy part: v_grouped = v_rel (1M 32B chunks over 2048 blocks) --
        const char* vb = (const char*)v;
        char* ob = (char*)out;
        long c0 = ((long)(b - 512) * 512 + tid) * 32;     // byte offset
        U4 r0 = ld_stream(vb + c0);
        U4 r1 = ld_stream(vb + c0 + 256 * 32);
        st_res(ob + c0,            r0);
        st_res(ob + c0 + 256 * 32, r1);
        return;
    }

    // ---- dm + dist broadcast part ----
    __shared__ __align__(32) float srow[256];
    __shared__ float sa[32], sw0[32], sw1[32], sb[32];
    __shared__ float sK;
    __shared__ int s_islast;
    if (tid < 32) {
        float scale = bn_gamma[tid] * rsqrtf(bn_var[tid] + EPS_BN);
        float w2o = w2[tid];
        sa[tid]  = w2o * scale;
        sw0[tid] = w1[tid * 2 + 0];
        sw1[tid] = w1[tid * 2 + 1];
        sb[tid]  = b1[tid];
        float kpart = w2o * (bn_beta[tid] - bn_mean[tid] * scale);
        #pragma unroll
        for (int off = 16; off > 0; off >>= 1)
            kpart += __shfl_down_sync(0xffffffffu, kpart, off);
        if (tid == 0) sK = kpart + b2[0];
    }
    __syncthreads();

    int n = b >> 1;
    int s = b & 1;
    int m = tid;
    // x[c][i] = v_rel[0, c, 127, i], layout (1,256,128,256)
    const int base = 127 * 256;
    float d0 = v[base + n] - v[base + m];
    float d1 = v[32768 + base + n] - v[32768 + base + m];

    float sp = sK, sn = sK;
    #pragma unroll
    for (int o = 0; o < 32; o++) {
        float lin = sw0[o] * d0 + sw1[o] * d1;
        sp += sa[o] * fmaxf(lin + sb[o], 0.0f);
        sn += sa[o] * fmaxf(sb[o] - lin, 0.0f);
    }
    float val = 0.5f * (expf(sp) + expf(sn));
    srow[m] = val;

    int anyok = __syncthreads_or((m < n) && (val <= TH));   // doubles as barrier
    if (s == 0) {
        g_dm[n * 256 + m] = val;
        if (tid == 0) g_rowok[n] = anyok;
    }

    // dist_mat_full broadcast: t-copies [s*64, s*64+64), 32B granularity.
    // row = 32 chunks of 32B; slice = 64 t-copies * 32 chunks = 2048 chunks.
    const U4* src = (const U4*)srow;
    char* dstb = (char*)(out + 8388864);
    int tbase = s * 64;
    #pragma unroll
    for (int k = 0; k < 8; k++) {
        int idx = tid + k * 256;        // 0..2047
        int t = tbase + (idx >> 5);
        int c = idx & 31;
        st_res(dstb + ((long)t * 8192 + n * 32 + c) * 32, src[c]);
    }

    if (s != 0) return;

    // ---- done-counter handshake: last slice-0 block computes groups ----
    if (tid == 0) {
        __threadfence();                       // commit g_dm row + rowok
        int old = atomicAdd(&g_done, 1);
        s_islast = (old == 255);
    }
    __syncthreads();
    if (!s_islast) return;
    __threadfence();                           // see all rows' writes

    float* __restrict__ out_gi = out + 8388608;
    int rowok = g_rowok[tid];
    bool fast = __syncthreads_and(tid == 0 || rowok);
    if (fast) {
        // every row r>=1 merges into the component labeled 0 -> all ranks 0
        out_gi[tid] = 0.0f;
    } else {
        // ---- exact fallback: row-parallel replica of reference lax.scan ----
        __shared__ int comp[256];
        __shared__ int firstidx[256];
        __shared__ int marked[256];
        __shared__ int cstar;
        __shared__ int newcomp;
        comp[tid] = tid;
        __syncthreads();

        for (int r = 1; r < 256; r++) {
            firstidx[tid] = 0x7fffffff;
            marked[tid] = 0;
            if (tid == 0) cstar = -1;
            __syncthreads();

            int myc = comp[tid];
            int rcomp = comp[r];
            bool okc = (tid < r) && (g_dm[r * 256 + tid] <= TH);
            if (okc) {
                atomicMin(&firstidx[myc], tid);
                marked[myc] = 1;
            }
            if (tid == r) marked[myc] = 1;
            __syncthreads();

            if (okc && myc != rcomp && firstidx[myc] == tid)
                atomicMax(&cstar, tid);
            __syncthreads();

            int cs = cstar;
            if (cs >= 0 && tid == cs) newcomp = myc;
            __syncthreads();
            if (cs >= 0 && marked[myc]) comp[tid] = newcomp;
            __syncthreads();
        }

        __shared__ int pres[256];
        pres[tid] = 0;
        __syncthreads();
        pres[comp[tid]] = 1;
        __syncthreads();
        for (int off = 1; off < 256; off <<= 1) {
            int t = (tid >= off) ? pres[tid - off] : 0;
            __syncthreads();
            pres[tid] += t;
            __syncthreads();
        }
        out_gi[tid] = (float)(pres[comp[tid]] - 1);
    }
    __syncthreads();
    if (tid == 0) g_done = 0;                  // reset for next graph replay
}

extern "C" void kernel_launch(void* const* d_in, const int* in_sizes, int n_in,
                              void* d_out, int out_size) {
    const float* v_rel    = (const float*)d_in[0];
    const float* w1       = (const float*)d_in[1];
    const float* b1       = (const float*)d_in[2];
    const float* bn_gamma = (const float*)d_in[3];
    const float* bn_beta  = (const float*)d_in[4];
    const float* bn_mean  = (const float*)d_in[5];
    const float* bn_var   = (const float*)d_in[6];
    const float* w2       = (const float*)d_in[7];
    const float* b2       = (const float*)d_in[8];
    float* out = (float*)d_out;

    fused_kernel<<<2560, 256>>>(v_rel, w1, b1, bn_gamma, bn_beta, bn_mean,
                                bn_var, w2, b2, out);
}